// round 8
// baseline (speedup 1.0000x reference)
#include <cuda_runtime.h>

#define S 64
#define MAXT 262144
#define L 512
#define NCMAX ((MAXT + L - 1) / L)

// ---- scratch (__device__ globals: no allocation allowed) ----
__device__ float g_e_buf[(size_t)MAXT * S];                    // e_t rows (+pad row)
__device__ int g_rollpad[MAXT + 96];                           // rolls padded with last value
__device__ unsigned char g_walk[(size_t)NCMAX * S * L];        // per-chunk walks (16 MB)
__device__ int g_boundary[NCMAX + 2];
__device__ int g_final_state;
__device__ float g_final_score;

__device__ __forceinline__ float fmax3(float a, float b, float c) {
    return fmaxf(fmaxf(a, b), c);
}

// Monotone fp32 <-> u32 key (total order == fp order; exact selection)
__device__ __forceinline__ unsigned int f2key(float f) {
    unsigned int u = __float_as_uint(f);
    return u ^ (((unsigned int)((int)u >> 31)) | 0x80000000u);
}
__device__ __forceinline__ float key2f(unsigned int k) {
    unsigned int u = k ^ (((unsigned int)((int)(~k) >> 31)) | 0x80000000u);
    return __uint_as_float(u);
}

// =====================================================================
// Kernel 0a: pad rolls so the serial loop needs no clamping
// =====================================================================
__global__ void prep_kernel(const int* __restrict__ rolls, int T)
{
    int i = blockIdx.x * blockDim.x + threadIdx.x;
    if (i < T + 96) g_rollpad[i] = rolls[(i < T) ? i : (T - 1)];
}

// Kernel 0b: no-op launch-index shims (keep ncu -s 5 landing on fwd_kernel)
__global__ void dummy_kernel() {}

// =====================================================================
// Kernel 1: serial Viterbi forward (values only). 256 threads, 8 warps.
// 4 lanes per state j = tid>>2; lane-group g = tid&3 covers i = 16g..16g+15.
// Combine via REDUX.UMAX on monotone keys over the 4-lane mask.
// =====================================================================
__global__ __launch_bounds__(256, 1)
void fwd_kernel(const int* __restrict__ rolls,
                const float* __restrict__ trans,
                const float* __restrict__ table, int T)
{
    __shared__ __align__(16) float smem_e[2][S];   // double-buffered e row
    __shared__ float smem_d[S];

    const int tid = threadIdx.x;
    const int j = tid >> 2;                        // state 0..63
    const int g = tid & 3;                         // candidate quarter
    const int l = tid & 31;
    const unsigned int mask = 0xFu << (l & 28);    // this state's 4 lanes

    float TR[16];
#pragma unroll
    for (int k = 0; k < 16; k++) TR[k] = trans[j * 65 + g * 16 + k];

    // ---- init: delta_0 = trans[:,64] + ll_0 ; e_1 = ll_1 + delta_0 ----
    {
        int r0 = rolls[0];
        int r1 = rolls[(T > 1) ? 1 : 0];
        float ll0 = table[r0 * S + j];
        float d0 = trans[j * 65 + 64] + ll0;
        if (T == 1 && g == 0) smem_d[j] = d0;
        float e1 = table[r1 * S + j] + d0;
        if (g == 0) smem_e[1][j] = e1;
        if (g == 1) g_e_buf[j] = e1;
    }
    // ll ring: llCur = ll_{t+1} at loop entry (t=1 -> ll_2), llNxt = ll_3
    float llCur = table[rolls[(T > 2) ? 2 : (T - 1)] * S + j];
    float llNxt = table[rolls[(T > 3) ? 3 : (T - 1)] * S + j];
    __syncthreads();

    float delta = 0.0f;

    // One step, STATIC parity RP/WP.
    // 4x LDS.128 (broadcast), 16 FFMA-imm (bit-exact add), quad-tree max,
    // REDUX.UMAX over the 4-lane group, inverse map, e = ll + delta.
#define VSTEP(RP, WP, tcur)                                                    \
    {                                                                          \
        int rn = g_rollpad[(tcur) + 3];                                        \
        float llN = table[rn * S + j];                                         \
        float mq[4];                                                           \
        {                                                                      \
            const float4* eb =                                                 \
                reinterpret_cast<const float4*>(smem_e[RP]) + g * 4;           \
            _Pragma("unroll")                                                  \
            for (int q = 0; q < 4; q++) {                                      \
                float4 f = eb[q];                                              \
                float a = __fmaf_rn(f.x, 1.0f, TR[4*q]);                       \
                float b = __fmaf_rn(f.y, 1.0f, TR[4*q+1]);                     \
                float c = __fmaf_rn(f.z, 1.0f, TR[4*q+2]);                     \
                float d = __fmaf_rn(f.w, 1.0f, TR[4*q+3]);                     \
                mq[q] = fmaxf(fmaxf(a, b), fmaxf(c, d));                       \
            }                                                                  \
        }                                                                      \
        float m = fmaxf(fmaxf(mq[0], mq[1]), fmaxf(mq[2], mq[3]));             \
        unsigned int rk = __reduce_max_sync(mask, f2key(m));                   \
        delta = key2f(rk);                                                     \
        float ep = llCur + delta;        /* e_{t+1} = ll_{t+1} + delta_t */    \
        if (g == 0) smem_e[WP][j] = ep;                                        \
        if (g == 1) g_e_buf[(size_t)(tcur) * S + j] = ep;                      \
        __syncthreads();                                                       \
        llCur = llNxt; llNxt = llN;                                            \
    }

    int t = 1;
    for (; t + 1 < T; t += 2) {        // t odd: read[1]->write[0]; then read[0]->write[1]
        VSTEP(1, 0, t);
        VSTEP(0, 1, t + 1);
    }
    if (t < T) {
        VSTEP(1, 0, t);
    }
#undef VSTEP

    if (T > 1 && g == 0) smem_d[j] = delta;
    __syncthreads();
    if (tid == 0) {
        float best = smem_d[0]; int bi = 0;
        for (int q = 1; q < S; q++) {           // first-argmax (strict >)
            float vq = smem_d[q];
            if (vq > best) { best = vq; bi = q; }
        }
        g_final_state = bi;
        g_final_score = best;
    }
}

// =====================================================================
// Kernel 2: per-chunk backpointer recompute (bit-identical candidates,
// first-argmax via ascending strict >) + all-64-endstate backtrack walks.
// =====================================================================
__global__ __launch_bounds__(512, 1)
void bp_chunk_kernel(const float* __restrict__ trans, int T)
{
    __shared__ signed char bp_s[L * S];                 // 32 KB
    __shared__ __align__(16) float se[8][S];
    const int c = blockIdx.x;
    const int tid = threadIdx.x;
    const int tg = tid >> 6;
    const int j = tid & 63;
    int nr = (T - 1) - c * L; if (nr > L) nr = L; if (nr < 0) nr = 0;

    float TRv[64];
#pragma unroll
    for (int i = 0; i < 64; i++) TRv[i] = trans[j * 65 + i];

    for (int k = 0; k < L / 8; k++) {
        const int r = k * 8 + tg;
        const bool act = r < nr;
        if (act) se[tg][j] = g_e_buf[((size_t)(c * L + r)) * S + j];
        __syncthreads();
        if (act) {
            const float4* ep = reinterpret_cast<const float4*>(se[tg]);
            float4 e0 = ep[0];
            float m = TRv[0] + e0.x; int a = 0;
            float cc = TRv[1] + e0.y; if (cc > m) { m = cc; a = 1; }
            cc = TRv[2] + e0.z; if (cc > m) { m = cc; a = 2; }
            cc = TRv[3] + e0.w; if (cc > m) { m = cc; a = 3; }
#pragma unroll
            for (int q = 1; q < 16; q++) {
                float4 ev = ep[q];
                cc = TRv[4*q]   + ev.x; if (cc > m) { m = cc; a = 4*q;   }
                cc = TRv[4*q+1] + ev.y; if (cc > m) { m = cc; a = 4*q+1; }
                cc = TRv[4*q+2] + ev.z; if (cc > m) { m = cc; a = 4*q+2; }
                cc = TRv[4*q+3] + ev.w; if (cc > m) { m = cc; a = 4*q+3; }
            }
            bp_s[r * S + j] = (signed char)a;
        }
        __syncthreads();
    }

    if (tid < S) {
        int s = tid;
        const size_t wb = ((size_t)c * S + tid) * L;
        if (nr < L) g_walk[wb + nr] = (unsigned char)s;
        for (int r = nr - 1; r >= 0; r--) {
            s = bp_s[r * S + s];
            g_walk[wb + r] = (unsigned char)s;
        }
    }
}

// =====================================================================
// Kernel 3: serial chunk-map composition -> per-chunk boundary states
// =====================================================================
__global__ void compose_kernel(int T)
{
    __shared__ unsigned char mp[L * S];
    int nc = (T >= 2) ? ((T - 2) / L + 1) : 1;
    for (int q = threadIdx.x; q < nc * S; q += blockDim.x)
        mp[q] = g_walk[(size_t)q * L];
    __syncthreads();
    if (threadIdx.x == 0) {
        int s = g_final_state;
        g_boundary[nc] = s;
        for (int c = nc - 1; c >= 0; c--) {
            s = mp[c * S + s];
            g_boundary[c] = s;
        }
    }
}

// =====================================================================
// Kernel 4: parallel path fill, reverse-time order: out[T-1-t] = s_t
// =====================================================================
__global__ void fill_kernel(float* __restrict__ out, int T, int out_size)
{
    const int c = blockIdx.x;
    const int m = threadIdx.x;
    const int t = c * L + m;
    if (t < T) {
        const int sel = g_boundary[c + 1];
        unsigned char s = g_walk[((size_t)c * S + sel) * L + m];
        const int oi = T - 1 - t;
        if (oi >= 0 && oi < out_size) out[oi] = (float)s;
    }
    if (c == 0 && m == 0 && T < out_size) out[T] = g_final_score;
}

// =====================================================================
extern "C" void kernel_launch(void* const* d_in, const int* in_sizes, int n_in,
                              void* d_out, int out_size)
{
    const int* rolls = nullptr;
    const float* trans = nullptr;
    const float* table = nullptr;
    int T = 0;
    for (int i = 0; i < n_in; i++) {
        const int sz = in_sizes[i];
        if (sz == 64 * 65)       trans = (const float*)d_in[i];
        else if (sz == 128 * 64) table = (const float*)d_in[i];
        else { rolls = (const int*)d_in[i]; T = sz; }
    }
    if (!rolls || !trans || !table || T < 1) return;
    if (T > MAXT) T = MAXT;

    int nc = (T >= 2) ? ((T - 2) / L + 1) : 1;

    // 3 launches ahead of fwd so ncu's fixed "-s 5 -c 1" window lands on fwd.
    prep_kernel<<<(T + 96 + 255) / 256, 256>>>(rolls, T);
    dummy_kernel<<<1, 32>>>();
    dummy_kernel<<<1, 32>>>();

    fwd_kernel<<<1, 256>>>(rolls, trans, table, T);
    bp_chunk_kernel<<<nc, 512>>>(trans, T);
    compose_kernel<<<1, 256>>>(T);
    fill_kernel<<<nc, L>>>((float*)d_out, T, out_size);
}

// round 9
// speedup vs baseline: 5.0631x; 5.0631x over previous
#include <cuda_runtime.h>

#define S 64
#define MAXT 262144
#define L 512
#define NCMAX ((MAXT + L - 1) / L)

// ---- scratch (__device__ globals: no allocation allowed) ----
__device__ float g_e_buf[(size_t)(MAXT + 8) * S];              // e_t rows (+pad rows)
__device__ int g_rollpad[MAXT + 96];                           // rolls padded with last value
__device__ unsigned char g_walk[(size_t)NCMAX * S * L];        // per-chunk walks (16 MB)
__device__ int g_boundary[NCMAX + 2];
__device__ int g_final_state;
__device__ float g_final_score;

__device__ __forceinline__ float fmax3(float a, float b, float c) {
    return fmaxf(fmaxf(a, b), c);
}

// =====================================================================
// Kernel 0a: pad rolls so the serial loop needs no clamping
// =====================================================================
__global__ void prep_kernel(const int* __restrict__ rolls, int T)
{
    int i = blockIdx.x * blockDim.x + threadIdx.x;
    if (i < T + 96) g_rollpad[i] = rolls[(i < T) ? i : (T - 1)];
}

// Kernel 0b: no-op launch-index shims (keep ncu -s 5 landing on fwd_kernel)
__global__ void dummy_kernel() {}

// =====================================================================
// Kernel 1: serial Viterbi forward (values only). 128 threads, 4 warps.
// Thread pair per state j: half=0 covers i 0..31, half=1 covers 32..63.
// R4 structure (proven best) + unroll-6 + FMNMX3-shaped tree.
// =====================================================================
__global__ __launch_bounds__(128, 1)
void fwd_kernel(const int* __restrict__ rolls,
                const float* __restrict__ trans,
                const float* __restrict__ table, int T)
{
    // padded e layout: i<32 at [i], i>=32 at [36+i-32] -> bank-disjoint halves
    __shared__ __align__(16) float smem_e[2][68];
    __shared__ float smem_d[S];

    const int tid = threadIdx.x;
    const int w = tid >> 5, l = tid & 31;
    const int j = w * 16 + (l >> 1);
    const int half = l & 1;
    const int ibase = half << 5;
    const bool lead = (half == 0);
    const int pos = (j < 32) ? j : (36 + (j - 32));
    const int ebOff = half ? 36 : 0;

    float TR[32];
#pragma unroll
    for (int k = 0; k < 32; k++) TR[k] = trans[j * 65 + ibase + k];

    // ---- init: delta_0 = trans[:,64] + ll_0 ; e_1 = ll_1 + delta_0 ----
    {
        int r0 = rolls[0];
        int r1 = rolls[(T > 1) ? 1 : 0];
        float ll0 = table[r0 * S + j];
        float d0 = trans[j * 65 + 64] + ll0;
        if (T == 1 && lead) smem_d[j] = d0;
        float e1 = table[r1 * S + j] + d0;
        if (lead) smem_e[1][pos] = e1;
        else      g_e_buf[j] = e1;
    }
    // ll ring: llCur = ll_{t+1} at loop entry (t=1 -> ll_2), llNxt = ll_3
    float llCur = table[rolls[(T > 2) ? 2 : (T - 1)] * S + j];
    float llNxt = table[rolls[(T > 3) ? 3 : (T - 1)] * S + j];

    const int* rp = g_rollpad + 4;                  // rollpad[t+3] at t=1
    float* epp = g_e_buf + (size_t)S + j;           // e-store row for t=1
    __syncthreads();

    float delta = 0.0f;

    // One step, STATIC parity RP/WP, static row offset OFF (0..5).
    // Candidates via FFMA-imm (E*1.0+TR bit-exact, rt=1); FMNMX3-shaped
    // selection tree (shape-free); shfl.bfly pair-combine.
#define VSTEP(RP, WP, OFF)                                                     \
    {                                                                          \
        int rn = rp[OFF];                                                      \
        float llN = table[rn * S + j];                                         \
        float mq[8];                                                           \
        {                                                                      \
            const float4* eb =                                                 \
                reinterpret_cast<const float4*>(&smem_e[RP][ebOff]);           \
            _Pragma("unroll")                                                  \
            for (int q = 0; q < 8; q++) {                                      \
                float4 f = eb[q];                                              \
                float a = __fmaf_rn(f.x, 1.0f, TR[4*q]);                       \
                float b = __fmaf_rn(f.y, 1.0f, TR[4*q+1]);                     \
                float c = __fmaf_rn(f.z, 1.0f, TR[4*q+2]);                     \
                float d = __fmaf_rn(f.w, 1.0f, TR[4*q+3]);                     \
                mq[q] = fmaxf(fmax3(a, b, c), d);                              \
            }                                                                  \
        }                                                                      \
        float r0 = fmax3(mq[0], mq[1], mq[2]);                                 \
        float r1 = fmax3(mq[3], mq[4], mq[5]);                                 \
        float r2 = fmaxf(mq[6], mq[7]);                                        \
        float m  = fmax3(r0, r1, r2);                                          \
        float mo = __shfl_xor_sync(0xffffffffu, m, 1);                         \
        delta = fmaxf(m, mo);                                                  \
        float ep = llCur + delta;        /* e_{t+1} = ll_{t+1} + delta_t */    \
        if (lead) smem_e[WP][pos] = ep;                                        \
        else      epp[(OFF) * S] = ep;                                         \
        __syncthreads();                                                       \
        llCur = llNxt; llNxt = llN;                                            \
    }

    int t = 1;
    // main loop: 6 steps/iter; t odd at entry: parities (1,0),(0,1) x3
    for (; t + 5 < T; t += 6) {
        VSTEP(1, 0, 0);
        VSTEP(0, 1, 1);
        VSTEP(1, 0, 2);
        VSTEP(0, 1, 3);
        VSTEP(1, 0, 4);
        VSTEP(0, 1, 5);
        rp += 6;
        epp += 6 * S;
    }
#undef VSTEP

    // tail (<=5 steps): runtime parity
    for (; t < T; t++) {
        const int rpar = t & 1, wpar = (t + 1) & 1;
        float mq[8];
        {
            const float4* eb = reinterpret_cast<const float4*>(&smem_e[rpar][ebOff]);
#pragma unroll
            for (int q = 0; q < 8; q++) {
                float4 f = eb[q];
                float a = __fmaf_rn(f.x, 1.0f, TR[4*q]);
                float b = __fmaf_rn(f.y, 1.0f, TR[4*q+1]);
                float c = __fmaf_rn(f.z, 1.0f, TR[4*q+2]);
                float d = __fmaf_rn(f.w, 1.0f, TR[4*q+3]);
                mq[q] = fmaxf(fmax3(a, b, c), d);
            }
        }
        float r0 = fmax3(mq[0], mq[1], mq[2]);
        float r1 = fmax3(mq[3], mq[4], mq[5]);
        float r2 = fmaxf(mq[6], mq[7]);
        float m  = fmax3(r0, r1, r2);
        float mo = __shfl_xor_sync(0xffffffffu, m, 1);
        delta = fmaxf(m, mo);
        float ep = llCur + delta;
        if (lead) smem_e[wpar][pos] = ep;
        else      g_e_buf[(size_t)t * S + j] = ep;
        __syncthreads();
        float llN = table[g_rollpad[t + 4] * S + j];
        llCur = llNxt; llNxt = llN;
    }

    if (T > 1 && lead) smem_d[j] = delta;
    __syncthreads();
    if (tid == 0) {
        float best = smem_d[0]; int bi = 0;
        for (int q = 1; q < S; q++) {           // first-argmax (strict >)
            float vq = smem_d[q];
            if (vq > best) { best = vq; bi = q; }
        }
        g_final_state = bi;
        g_final_score = best;
    }
}

// =====================================================================
// Kernel 2: per-chunk backpointer recompute (bit-identical candidates,
// first-argmax via ascending strict >) + all-64-endstate backtrack walks.
// =====================================================================
__global__ __launch_bounds__(512, 1)
void bp_chunk_kernel(const float* __restrict__ trans, int T)
{
    __shared__ signed char bp_s[L * S];                 // 32 KB
    __shared__ __align__(16) float se[8][S];
    const int c = blockIdx.x;
    const int tid = threadIdx.x;
    const int tg = tid >> 6;
    const int j = tid & 63;
    int nr = (T - 1) - c * L; if (nr > L) nr = L; if (nr < 0) nr = 0;

    float TRv[64];
#pragma unroll
    for (int i = 0; i < 64; i++) TRv[i] = trans[j * 65 + i];

    for (int k = 0; k < L / 8; k++) {
        const int r = k * 8 + tg;
        const bool act = r < nr;
        if (act) se[tg][j] = g_e_buf[((size_t)(c * L + r)) * S + j];
        __syncthreads();
        if (act) {
            const float4* ep = reinterpret_cast<const float4*>(se[tg]);
            float4 e0 = ep[0];
            float m = TRv[0] + e0.x; int a = 0;
            float cc = TRv[1] + e0.y; if (cc > m) { m = cc; a = 1; }
            cc = TRv[2] + e0.z; if (cc > m) { m = cc; a = 2; }
            cc = TRv[3] + e0.w; if (cc > m) { m = cc; a = 3; }
#pragma unroll
            for (int q = 1; q < 16; q++) {
                float4 ev = ep[q];
                cc = TRv[4*q]   + ev.x; if (cc > m) { m = cc; a = 4*q;   }
                cc = TRv[4*q+1] + ev.y; if (cc > m) { m = cc; a = 4*q+1; }
                cc = TRv[4*q+2] + ev.z; if (cc > m) { m = cc; a = 4*q+2; }
                cc = TRv[4*q+3] + ev.w; if (cc > m) { m = cc; a = 4*q+3; }
            }
            bp_s[r * S + j] = (signed char)a;
        }
        __syncthreads();
    }

    if (tid < S) {
        int s = tid;
        const size_t wb = ((size_t)c * S + tid) * L;
        if (nr < L) g_walk[wb + nr] = (unsigned char)s;
        for (int r = nr - 1; r >= 0; r--) {
            s = bp_s[r * S + s];
            g_walk[wb + r] = (unsigned char)s;
        }
    }
}

// =====================================================================
// Kernel 3: serial chunk-map composition -> per-chunk boundary states
// =====================================================================
__global__ void compose_kernel(int T)
{
    __shared__ unsigned char mp[L * S];
    int nc = (T >= 2) ? ((T - 2) / L + 1) : 1;
    for (int q = threadIdx.x; q < nc * S; q += blockDim.x)
        mp[q] = g_walk[(size_t)q * L];
    __syncthreads();
    if (threadIdx.x == 0) {
        int s = g_final_state;
        g_boundary[nc] = s;
        for (int c = nc - 1; c >= 0; c--) {
            s = mp[c * S + s];
            g_boundary[c] = s;
        }
    }
}

// =====================================================================
// Kernel 4: parallel path fill, reverse-time order: out[T-1-t] = s_t
// =====================================================================
__global__ void fill_kernel(float* __restrict__ out, int T, int out_size)
{
    const int c = blockIdx.x;
    const int m = threadIdx.x;
    const int t = c * L + m;
    if (t < T) {
        const int sel = g_boundary[c + 1];
        unsigned char s = g_walk[((size_t)c * S + sel) * L + m];
        const int oi = T - 1 - t;
        if (oi >= 0 && oi < out_size) out[oi] = (float)s;
    }
    if (c == 0 && m == 0 && T < out_size) out[T] = g_final_score;
}

// =====================================================================
extern "C" void kernel_launch(void* const* d_in, const int* in_sizes, int n_in,
                              void* d_out, int out_size)
{
    const int* rolls = nullptr;
    const float* trans = nullptr;
    const float* table = nullptr;
    int T = 0;
    for (int i = 0; i < n_in; i++) {
        const int sz = in_sizes[i];
        if (sz == 64 * 65)       trans = (const float*)d_in[i];
        else if (sz == 128 * 64) table = (const float*)d_in[i];
        else { rolls = (const int*)d_in[i]; T = sz; }
    }
    if (!rolls || !trans || !table || T < 1) return;
    if (T > MAXT) T = MAXT;

    int nc = (T >= 2) ? ((T - 2) / L + 1) : 1;

    // 3 launches ahead of fwd so ncu's fixed "-s 5 -c 1" window lands on fwd.
    prep_kernel<<<(T + 96 + 255) / 256, 256>>>(rolls, T);
    dummy_kernel<<<1, 32>>>();
    dummy_kernel<<<1, 32>>>();

    fwd_kernel<<<1, 128>>>(rolls, trans, table, T);
    bp_chunk_kernel<<<nc, 512>>>(trans, T);
    compose_kernel<<<1, 256>>>(T);
    fill_kernel<<<nc, L>>>((float*)d_out, T, out_size);
}